// round 1
// baseline (speedup 1.0000x reference)
#include <cuda_runtime.h>
#include <cuda_bf16.h>
#include <cstdint>

#define NN   10000
#define BB   32
#define DIN  2
#define HH   64
#define GIN  66              // DIN + HH
#define CC   (GIN*BB)        // 2112
#define MHOP 3
#define KF   (GIN*MHOP)      // 198

// ------------------------- scratch (device globals; no allocation) -------------------------
__device__ __nv_bfloat16 g_Abf[(size_t)NN*NN];      // 200 MB  bf16 support matrix
__device__ __nv_bfloat16 g_Xbf[(size_t)NN*CC];      // hop-0 operand (bf16), reused gconv1/2
__device__ __nv_bfloat16 g_Pbf[(size_t)NN*CC];      // hop-1 operand (bf16)
__device__ float         g_Xf [(size_t)NN*CC];      // hop-0 features fp32
__device__ float         g_P1f[(size_t)NN*CC];      // hop-1 features fp32
__device__ float         g_P2f[(size_t)NN*CC];      // hop-2 features fp32
__device__ float         g_rs [(size_t)BB*NN*HH];   // r * states
__device__ float         g_u  [(size_t)BB*NN*HH];   // u gate

// ------------------------- A fp32 -> bf16 -------------------------
__global__ void k_convertA(const float* __restrict__ A) {
    size_t i = ((size_t)blockIdx.x*blockDim.x + threadIdx.x)*4;
    if (i >= (size_t)NN*NN) return;
    float4 v = *(const float4*)(A + i);
    __nv_bfloat162 lo = __float22bfloat162_rn(make_float2(v.x, v.y));
    __nv_bfloat162 hi = __float22bfloat162_rn(make_float2(v.z, v.w));
    ((__nv_bfloat162*)(g_Abf + i))[0] = lo;
    ((__nv_bfloat162*)(g_Abf + i))[1] = hi;
}

// ------------------------- build X = concat(inputs, s)  ->  [N][CC], c = d*32+b ------------
__global__ void k_buildX(const float* __restrict__ inputs, const float* __restrict__ st, int useRS) {
    int idx = blockIdx.x*blockDim.x + threadIdx.x;
    if (idx >= NN*CC) return;
    int n = idx / CC, c = idx % CC;
    int d = c >> 5, b = c & 31;
    float v;
    if (d < DIN)       v = inputs[((size_t)b*NN + n)*DIN + d];
    else if (useRS)    v = g_rs  [((size_t)b*NN + n)*HH  + (d-DIN)];
    else               v = st    [((size_t)b*NN + n)*HH  + (d-DIN)];
    g_Xf [idx] = v;
    g_Xbf[idx] = __float2bfloat16(v);
}

// ------------------------- big GEMM: P = A(bf16) @ B(bf16), fp32 accum ---------------------
// mode 0: B = g_Xbf,  out fp32 -> g_P1f  and bf16 -> g_Pbf
// mode 1: B = g_Pbf,  out fp32 -> g_P2f = 2*acc - g_Xf
#define BM   128
#define BN   128
#define BKK  32
#define LDAS 40      // BKK + 8 pad  (conflict-free ldmatrix)
#define LDBS 136     // BN  + 8 pad

__global__ __launch_bounds__(256) void k_gemmA(int mode)
{
    __shared__ __nv_bfloat16 As[2][BM*LDAS];
    __shared__ __nv_bfloat16 Bs[2][BKK*LDBS];

    const __nv_bfloat16* __restrict__ Bmat = (mode == 0) ? g_Xbf : g_Pbf;
    float* __restrict__ outF = (mode == 0) ? g_P1f : g_P2f;

    const int tid  = threadIdx.x;
    const int lane = tid & 31, warp = tid >> 5;
    const int wm = warp >> 1, wn = warp & 1;         // 4 x 2 warps, 32 x 64 warp tile
    const int bm0 = blockIdx.y * BM;
    const int bn0 = blockIdx.x * BN;

    float acc[2][8][4];
    #pragma unroll
    for (int i=0;i<2;i++)
        #pragma unroll
        for (int j=0;j<8;j++)
            #pragma unroll
            for (int q=0;q<4;q++) acc[i][j][q]=0.f;

    const int KT = (NN + BKK - 1)/BKK;               // 313

    auto load_tiles = [&](int kt, int buf) {
        int k0 = kt * BKK;
        #pragma unroll
        for (int i = 0; i < 2; i++) {                // A tile: 128 x 32
            int q  = tid + i*256;
            int ar = q >> 2, ac = (q & 3) * 8;
            const __nv_bfloat16* gp = g_Abf + (size_t)(bm0 + ar)*NN + (k0 + ac);
            int bytes = ((bm0 + ar) < NN && (k0 + ac) < NN) ? 16 : 0;
            if (!bytes) gp = g_Abf;
            uint32_t sa = (uint32_t)__cvta_generic_to_shared(&As[buf][ar*LDAS + ac]);
            asm volatile("cp.async.cg.shared.global [%0], [%1], 16, %2;\n"
                         :: "r"(sa), "l"(gp), "r"(bytes));
        }
        #pragma unroll
        for (int i = 0; i < 2; i++) {                // B tile: 32 x 128
            int q  = tid + i*256;
            int br = q >> 4, bc = (q & 15) * 8;
            const __nv_bfloat16* gp = Bmat + (size_t)(k0 + br)*CC + (bn0 + bc);
            int bytes = ((k0 + br) < NN && (bn0 + bc) < CC) ? 16 : 0;
            if (!bytes) gp = Bmat;
            uint32_t sa = (uint32_t)__cvta_generic_to_shared(&Bs[buf][br*LDBS + bc]);
            asm volatile("cp.async.cg.shared.global [%0], [%1], 16, %2;\n"
                         :: "r"(sa), "l"(gp), "r"(bytes));
        }
    };

    load_tiles(0, 0);
    asm volatile("cp.async.commit_group;\n" ::: "memory");

    for (int kt = 0; kt < KT; kt++) {
        int buf = kt & 1;
        if (kt + 1 < KT) {
            load_tiles(kt+1, buf^1);
            asm volatile("cp.async.commit_group;\n" ::: "memory");
            asm volatile("cp.async.wait_group 1;\n" ::: "memory");
        } else {
            asm volatile("cp.async.wait_group 0;\n" ::: "memory");
        }
        __syncthreads();

        #pragma unroll
        for (int kk = 0; kk < 2; kk++) {
            uint32_t a[2][4];
            #pragma unroll
            for (int mi = 0; mi < 2; mi++) {
                int r = wm*32 + mi*16 + (lane & 15);
                int c = kk*16 + (lane >> 4)*8;
                uint32_t sa = (uint32_t)__cvta_generic_to_shared(&As[buf][r*LDAS + c]);
                asm volatile("ldmatrix.sync.aligned.m8n8.x4.shared.b16 {%0,%1,%2,%3}, [%4];\n"
                    : "=r"(a[mi][0]),"=r"(a[mi][1]),"=r"(a[mi][2]),"=r"(a[mi][3]) : "r"(sa));
            }
            uint32_t b[8][2];
            #pragma unroll
            for (int nj = 0; nj < 4; nj++) {
                int r = kk*16 + (lane & 15);
                int c = wn*64 + nj*16 + (lane >> 4)*8;
                uint32_t sa = (uint32_t)__cvta_generic_to_shared(&Bs[buf][r*LDBS + c]);
                asm volatile("ldmatrix.sync.aligned.m8n8.x4.trans.shared.b16 {%0,%1,%2,%3}, [%4];\n"
                    : "=r"(b[2*nj][0]),"=r"(b[2*nj][1]),"=r"(b[2*nj+1][0]),"=r"(b[2*nj+1][1]) : "r"(sa));
            }
            #pragma unroll
            for (int mi = 0; mi < 2; mi++)
                #pragma unroll
                for (int ni = 0; ni < 8; ni++) {
                    asm volatile("mma.sync.aligned.m16n8k16.row.col.f32.bf16.bf16.f32 "
                        "{%0,%1,%2,%3}, {%4,%5,%6,%7}, {%8,%9}, {%0,%1,%2,%3};\n"
                        : "+f"(acc[mi][ni][0]),"+f"(acc[mi][ni][1]),
                          "+f"(acc[mi][ni][2]),"+f"(acc[mi][ni][3])
                        : "r"(a[mi][0]),"r"(a[mi][1]),"r"(a[mi][2]),"r"(a[mi][3]),
                          "r"(b[ni][0]),"r"(b[ni][1]));
                }
        }
        __syncthreads();
    }

    // epilogue
    #pragma unroll
    for (int mi = 0; mi < 2; mi++) {
        #pragma unroll
        for (int ni = 0; ni < 8; ni++) {
            int col = bn0 + wn*64 + ni*8 + (lane & 3)*2;
            #pragma unroll
            for (int h = 0; h < 2; h++) {
                int row = bm0 + wm*32 + mi*16 + (lane >> 2) + h*8;
                if (row < NN && col < CC) {
                    float v0 = acc[mi][ni][2*h], v1 = acc[mi][ni][2*h+1];
                    size_t o = (size_t)row*CC + col;
                    if (mode == 1) {
                        v0 = 2.f*v0 - g_Xf[o];
                        v1 = 2.f*v1 - g_Xf[o+1];
                    }
                    outF[o]   = v0;
                    outF[o+1] = v1;
                    if (mode == 0) {
                        __nv_bfloat162 p = __float22bfloat162_rn(make_float2(v0, v1));
                        *(__nv_bfloat162*)(g_Pbf + o) = p;
                    }
                }
            }
        }
    }
}

// ------------------------- feature GEMM (ru): K=198 -> 128, sigmoid, emit r*s and u ---------
__global__ __launch_bounds__(256) void k_featRU(
    const float* __restrict__ Wru, const float* __restrict__ bru,
    const float* __restrict__ states)
{
    __shared__ float fs[KF*36];
    int n = blockIdx.x;
    int t = threadIdx.x;
    for (int idx = t; idx < KF*BB; idx += 256) {
        int d = idx / (MHOP*BB);
        int rem = idx % (MHOP*BB);
        int m = rem >> 5, b = rem & 31;
        const float* src = (m==0)? g_Xf : (m==1)? g_P1f : g_P2f;
        fs[(d*MHOP + m)*36 + b] = src[(size_t)n*CC + d*BB + b];
    }
    __syncthreads();

    int c4 = (t & 31) * 4;
    int b4 = (t >> 5) * 4;
    float accv[4][4] = {};
    for (int k = 0; k < KF; k++) {
        float4 w = *(const float4*)(Wru + k*128 + c4);
        float4 f = *(const float4*)(&fs[k*36 + b4]);
        float wv[4] = {w.x,w.y,w.z,w.w};
        float fv[4] = {f.x,f.y,f.z,f.w};
        #pragma unroll
        for (int i=0;i<4;i++)
            #pragma unroll
            for (int j=0;j<4;j++)
                accv[i][j] += fv[i]*wv[j];
    }
    #pragma unroll
    for (int i=0;i<4;i++) {
        int b = b4 + i;
        #pragma unroll
        for (int j=0;j<4;j++) {
            int o = c4 + j;
            float z = accv[i][j] + bru[o];
            float s = 1.f/(1.f + __expf(-z));
            if (o < HH) {
                size_t oi = ((size_t)b*NN + n)*HH + o;
                g_rs[oi] = s * states[oi];
            } else {
                size_t oi = ((size_t)b*NN + n)*HH + (o - HH);
                g_u[oi] = s;
            }
        }
    }
}

// ------------------------- feature GEMM (c): K=198 -> 64, tanh, final gate -----------------
__global__ __launch_bounds__(256) void k_featC(
    const float* __restrict__ Wc, const float* __restrict__ bc,
    const float* __restrict__ states, float* __restrict__ out)
{
    __shared__ float fs[KF*36];
    int n = blockIdx.x;
    int t = threadIdx.x;
    for (int idx = t; idx < KF*BB; idx += 256) {
        int d = idx / (MHOP*BB);
        int rem = idx % (MHOP*BB);
        int m = rem >> 5, b = rem & 31;
        const float* src = (m==0)? g_Xf : (m==1)? g_P1f : g_P2f;
        fs[(d*MHOP + m)*36 + b] = src[(size_t)n*CC + d*BB + b];
    }
    __syncthreads();

    int c4 = (t & 15) * 4;
    int b2 = (t >> 4) * 2;
    float accv[2][4] = {};
    for (int k = 0; k < KF; k++) {
        float4 w = *(const float4*)(Wc + k*64 + c4);
        float2 f = *(const float2*)(&fs[k*36 + b2]);
        float wv[4] = {w.x,w.y,w.z,w.w};
        float fv[2] = {f.x,f.y};
        #pragma unroll
        for (int i=0;i<2;i++)
            #pragma unroll
            for (int j=0;j<4;j++)
                accv[i][j] += fv[i]*wv[j];
    }
    #pragma unroll
    for (int i=0;i<2;i++) {
        int b = b2 + i;
        #pragma unroll
        for (int j=0;j<4;j++) {
            int o = c4 + j;
            float cz = tanhf(accv[i][j] + bc[o]);
            size_t oi = ((size_t)b*NN + n)*HH + o;
            float u = g_u[oi];
            out[oi] = u*states[oi] + (1.f - u)*cz;
        }
    }
}

// ------------------------- launch -------------------------
extern "C" void kernel_launch(void* const* d_in, const int* in_sizes, int n_in,
                              void* d_out, int out_size) {
    const float* inputs = (const float*)d_in[0];
    const float* states = (const float*)d_in[1];
    const float* A      = (const float*)d_in[2];
    const float* W_ru   = (const float*)d_in[3];
    const float* b_ru   = (const float*)d_in[4];
    const float* W_c    = (const float*)d_in[5];
    const float* b_c    = (const float*)d_in[6];
    float* out = (float*)d_out;

    dim3 gemmGrid((CC + BN - 1)/BN, (NN + BM - 1)/BM);   // 17 x 79

    k_convertA<<<(NN*(size_t)NN/4 + 255)/256, 256>>>(A);

    // gconv 1: x = [inputs, states]
    k_buildX<<<(NN*CC + 255)/256, 256>>>(inputs, states, 0);
    k_gemmA<<<gemmGrid, 256>>>(0);                       // P1 = A @ X
    k_gemmA<<<gemmGrid, 256>>>(1);                       // P2 = 2 A @ P1 - X
    k_featRU<<<NN, 256>>>(W_ru, b_ru, states);           // sigmoid, r*s, u

    // gconv 2: x = [inputs, r*states]
    k_buildX<<<(NN*CC + 255)/256, 256>>>(inputs, states, 1);
    k_gemmA<<<gemmGrid, 256>>>(0);                       // Q1
    k_gemmA<<<gemmGrid, 256>>>(1);                       // Q2
    k_featC<<<NN, 256>>>(W_c, b_c, states, out);         // tanh + u*s + (1-u)*c
}

// round 3
// speedup vs baseline: 1.0002x; 1.0002x over previous
#include <cuda_runtime.h>
#include <cuda_bf16.h>
#include <cstdint>

#define NN   10000
#define BB   32
#define DIN  2
#define HH   64
#define GIN  66              // DIN + HH
#define CC   (GIN*BB)        // 2112
#define MHOP 3
#define KF   (GIN*MHOP)      // 198

// ------------------------- scratch (device globals; no allocation) -------------------------
__device__ __nv_bfloat16 g_Abf[(size_t)NN*NN];      // 200 MB  bf16 support matrix
__device__ __nv_bfloat16 g_Xbf[(size_t)NN*CC];      // hop-0 operand (bf16), reused gconv1/2
__device__ __nv_bfloat16 g_Pbf[(size_t)NN*CC];      // hop-1 operand (bf16)
__device__ float         g_Xf [(size_t)NN*CC];      // hop-0 features fp32
__device__ float         g_P1f[(size_t)NN*CC];      // hop-1 features fp32
__device__ float         g_P2f[(size_t)NN*CC];      // hop-2 features fp32
__device__ float         g_rs [(size_t)BB*NN*HH];   // r * states
__device__ float         g_u  [(size_t)BB*NN*HH];   // u gate

// ------------------------- A fp32 -> bf16 -------------------------
__global__ void k_convertA(const float* __restrict__ A) {
    size_t i = ((size_t)blockIdx.x*blockDim.x + threadIdx.x)*4;
    if (i >= (size_t)NN*NN) return;
    float4 v = *(const float4*)(A + i);
    __nv_bfloat162 lo = __float22bfloat162_rn(make_float2(v.x, v.y));
    __nv_bfloat162 hi = __float22bfloat162_rn(make_float2(v.z, v.w));
    ((__nv_bfloat162*)(g_Abf + i))[0] = lo;
    ((__nv_bfloat162*)(g_Abf + i))[1] = hi;
}

// ------------------------- build X = concat(inputs, s)  ->  [N][CC], c = d*32+b ------------
__global__ void k_buildX(const float* __restrict__ inputs, const float* __restrict__ st, int useRS) {
    int idx = blockIdx.x*blockDim.x + threadIdx.x;
    if (idx >= NN*CC) return;
    int n = idx / CC, c = idx % CC;
    int d = c >> 5, b = c & 31;
    float v;
    if (d < DIN)       v = inputs[((size_t)b*NN + n)*DIN + d];
    else if (useRS)    v = g_rs  [((size_t)b*NN + n)*HH  + (d-DIN)];
    else               v = st    [((size_t)b*NN + n)*HH  + (d-DIN)];
    g_Xf [idx] = v;
    g_Xbf[idx] = __float2bfloat16(v);
}

// ------------------------- big GEMM: P = A(bf16) @ B(bf16), fp32 accum ---------------------
// mode 0: B = g_Xbf,  out fp32 -> g_P1f  and bf16 -> g_Pbf
// mode 1: B = g_Pbf,  out fp32 -> g_P2f = 2*acc - g_Xf
#define BM   128
#define BN   128
#define BKK  32
#define LDAS 40      // BKK + 8 pad  (conflict-free ldmatrix)
#define LDBS 136     // BN  + 8 pad

__global__ __launch_bounds__(256) void k_gemmA(int mode)
{
    __shared__ __nv_bfloat16 As[2][BM*LDAS];
    __shared__ __nv_bfloat16 Bs[2][BKK*LDBS];

    const __nv_bfloat16* __restrict__ Bmat = (mode == 0) ? g_Xbf : g_Pbf;
    float* __restrict__ outF = (mode == 0) ? g_P1f : g_P2f;

    const int tid  = threadIdx.x;
    const int lane = tid & 31, warp = tid >> 5;
    const int wm = warp >> 1, wn = warp & 1;         // 4 x 2 warps, 32 x 64 warp tile
    const int bm0 = blockIdx.y * BM;
    const int bn0 = blockIdx.x * BN;

    float acc[2][8][4];
    #pragma unroll
    for (int i=0;i<2;i++)
        #pragma unroll
        for (int j=0;j<8;j++)
            #pragma unroll
            for (int q=0;q<4;q++) acc[i][j][q]=0.f;

    const int KT = (NN + BKK - 1)/BKK;               // 313

    auto load_tiles = [&](int kt, int buf) {
        int k0 = kt * BKK;
        #pragma unroll
        for (int i = 0; i < 2; i++) {                // A tile: 128 x 32
            int q  = tid + i*256;
            int ar = q >> 2, ac = (q & 3) * 8;
            const __nv_bfloat16* gp = g_Abf + (size_t)(bm0 + ar)*NN + (k0 + ac);
            int bytes = ((bm0 + ar) < NN && (k0 + ac) < NN) ? 16 : 0;
            if (!bytes) gp = g_Abf;
            uint32_t sa = (uint32_t)__cvta_generic_to_shared(&As[buf][ar*LDAS + ac]);
            asm volatile("cp.async.cg.shared.global [%0], [%1], 16, %2;\n"
                         :: "r"(sa), "l"(gp), "r"(bytes));
        }
        #pragma unroll
        for (int i = 0; i < 2; i++) {                // B tile: 32 x 128
            int q  = tid + i*256;
            int br = q >> 4, bc = (q & 15) * 8;
            const __nv_bfloat16* gp = Bmat + (size_t)(k0 + br)*CC + (bn0 + bc);
            int bytes = ((k0 + br) < NN && (bn0 + bc) < CC) ? 16 : 0;
            if (!bytes) gp = Bmat;
            uint32_t sa = (uint32_t)__cvta_generic_to_shared(&Bs[buf][br*LDBS + bc]);
            asm volatile("cp.async.cg.shared.global [%0], [%1], 16, %2;\n"
                         :: "r"(sa), "l"(gp), "r"(bytes));
        }
    };

    load_tiles(0, 0);
    asm volatile("cp.async.commit_group;\n" ::: "memory");

    for (int kt = 0; kt < KT; kt++) {
        int buf = kt & 1;
        if (kt + 1 < KT) {
            load_tiles(kt+1, buf^1);
            asm volatile("cp.async.commit_group;\n" ::: "memory");
            asm volatile("cp.async.wait_group 1;\n" ::: "memory");
        } else {
            asm volatile("cp.async.wait_group 0;\n" ::: "memory");
        }
        __syncthreads();

        #pragma unroll
        for (int kk = 0; kk < 2; kk++) {
            uint32_t a[2][4];
            #pragma unroll
            for (int mi = 0; mi < 2; mi++) {
                int r = wm*32 + mi*16 + (lane & 15);
                int c = kk*16 + (lane >> 4)*8;
                uint32_t sa = (uint32_t)__cvta_generic_to_shared(&As[buf][r*LDAS + c]);
                asm volatile("ldmatrix.sync.aligned.m8n8.x4.shared.b16 {%0,%1,%2,%3}, [%4];\n"
                    : "=r"(a[mi][0]),"=r"(a[mi][1]),"=r"(a[mi][2]),"=r"(a[mi][3]) : "r"(sa));
            }
            uint32_t b[8][2];
            #pragma unroll
            for (int nj = 0; nj < 4; nj++) {
                int r = kk*16 + (lane & 15);
                int c = wn*64 + nj*16 + (lane >> 4)*8;
                uint32_t sa = (uint32_t)__cvta_generic_to_shared(&Bs[buf][r*LDBS + c]);
                asm volatile("ldmatrix.sync.aligned.m8n8.x4.trans.shared.b16 {%0,%1,%2,%3}, [%4];\n"
                    : "=r"(b[2*nj][0]),"=r"(b[2*nj][1]),"=r"(b[2*nj+1][0]),"=r"(b[2*nj+1][1]) : "r"(sa));
            }
            #pragma unroll
            for (int mi = 0; mi < 2; mi++)
                #pragma unroll
                for (int ni = 0; ni < 8; ni++) {
                    asm volatile("mma.sync.aligned.m16n8k16.row.col.f32.bf16.bf16.f32 "
                        "{%0,%1,%2,%3}, {%4,%5,%6,%7}, {%8,%9}, {%0,%1,%2,%3};\n"
                        : "+f"(acc[mi][ni][0]),"+f"(acc[mi][ni][1]),
                          "+f"(acc[mi][ni][2]),"+f"(acc[mi][ni][3])
                        : "r"(a[mi][0]),"r"(a[mi][1]),"r"(a[mi][2]),"r"(a[mi][3]),
                          "r"(b[ni][0]),"r"(b[ni][1]));
                }
        }
        __syncthreads();
    }

    // epilogue
    #pragma unroll
    for (int mi = 0; mi < 2; mi++) {
        #pragma unroll
        for (int ni = 0; ni < 8; ni++) {
            int col = bn0 + wn*64 + ni*8 + (lane & 3)*2;
            #pragma unroll
            for (int h = 0; h < 2; h++) {
                int row = bm0 + wm*32 + mi*16 + (lane >> 2) + h*8;
                if (row < NN && col < CC) {
                    float v0 = acc[mi][ni][2*h], v1 = acc[mi][ni][2*h+1];
                    size_t o = (size_t)row*CC + col;
                    if (mode == 1) {
                        v0 = 2.f*v0 - g_Xf[o];
                        v1 = 2.f*v1 - g_Xf[o+1];
                    }
                    outF[o]   = v0;
                    outF[o+1] = v1;
                    if (mode == 0) {
                        __nv_bfloat162 p = __float22bfloat162_rn(make_float2(v0, v1));
                        *(__nv_bfloat162*)(g_Pbf + o) = p;
                    }
                }
            }
        }
    }
}

// ------------------------- feature GEMM (ru): K=198 -> 128, sigmoid, emit r*s and u ---------
__global__ __launch_bounds__(256) void k_featRU(
    const float* __restrict__ Wru, const float* __restrict__ bru,
    const float* __restrict__ states)
{
    __shared__ float fs[KF*36];
    int n = blockIdx.x;
    int t = threadIdx.x;
    for (int idx = t; idx < KF*BB; idx += 256) {
        int d = idx / (MHOP*BB);
        int rem = idx % (MHOP*BB);
        int m = rem >> 5, b = rem & 31;
        const float* src = (m==0)? g_Xf : (m==1)? g_P1f : g_P2f;
        fs[(d*MHOP + m)*36 + b] = src[(size_t)n*CC + d*BB + b];
    }
    __syncthreads();

    int c4 = (t & 31) * 4;
    int b4 = (t >> 5) * 4;
    float accv[4][4] = {};
    for (int k = 0; k < KF; k++) {
        float4 w = *(const float4*)(Wru + k*128 + c4);
        float4 f = *(const float4*)(&fs[k*36 + b4]);
        float wv[4] = {w.x,w.y,w.z,w.w};
        float fv[4] = {f.x,f.y,f.z,f.w};
        #pragma unroll
        for (int i=0;i<4;i++)
            #pragma unroll
            for (int j=0;j<4;j++)
                accv[i][j] += fv[i]*wv[j];
    }
    #pragma unroll
    for (int i=0;i<4;i++) {
        int b = b4 + i;
        #pragma unroll
        for (int j=0;j<4;j++) {
            int o = c4 + j;
            float z = accv[i][j] + bru[o];
            float s = 1.f/(1.f + __expf(-z));
            if (o < HH) {
                size_t oi = ((size_t)b*NN + n)*HH + o;
                g_rs[oi] = s * states[oi];
            } else {
                size_t oi = ((size_t)b*NN + n)*HH + (o - HH);
                g_u[oi] = s;
            }
        }
    }
}

// ------------------------- feature GEMM (c): K=198 -> 64, tanh, final gate -----------------
__global__ __launch_bounds__(256) void k_featC(
    const float* __restrict__ Wc, const float* __restrict__ bc,
    const float* __restrict__ states, float* __restrict__ out)
{
    __shared__ float fs[KF*36];
    int n = blockIdx.x;
    int t = threadIdx.x;
    for (int idx = t; idx < KF*BB; idx += 256) {
        int d = idx / (MHOP*BB);
        int rem = idx % (MHOP*BB);
        int m = rem >> 5, b = rem & 31;
        const float* src = (m==0)? g_Xf : (m==1)? g_P1f : g_P2f;
        fs[(d*MHOP + m)*36 + b] = src[(size_t)n*CC + d*BB + b];
    }
    __syncthreads();

    int c4 = (t & 15) * 4;
    int b2 = (t >> 4) * 2;
    float accv[2][4] = {};
    for (int k = 0; k < KF; k++) {
        float4 w = *(const float4*)(Wc + k*64 + c4);
        float2 f = *(const float2*)(&fs[k*36 + b2]);
        float wv[4] = {w.x,w.y,w.z,w.w};
        float fv[2] = {f.x,f.y};
        #pragma unroll
        for (int i=0;i<2;i++)
            #pragma unroll
            for (int j=0;j<4;j++)
                accv[i][j] += fv[i]*wv[j];
    }
    #pragma unroll
    for (int i=0;i<2;i++) {
        int b = b2 + i;
        #pragma unroll
        for (int j=0;j<4;j++) {
            int o = c4 + j;
            float cz = tanhf(accv[i][j] + bc[o]);
            size_t oi = ((size_t)b*NN + n)*HH + o;
            float u = g_u[oi];
            out[oi] = u*states[oi] + (1.f - u)*cz;
        }
    }
}

// ------------------------- launch -------------------------
extern "C" void kernel_launch(void* const* d_in, const int* in_sizes, int n_in,
                              void* d_out, int out_size) {
    const float* inputs = (const float*)d_in[0];
    const float* states = (const float*)d_in[1];
    const float* A      = (const float*)d_in[2];
    const float* W_ru   = (const float*)d_in[3];
    const float* b_ru   = (const float*)d_in[4];
    const float* W_c    = (const float*)d_in[5];
    const float* b_c    = (const float*)d_in[6];
    float* out = (float*)d_out;

    dim3 gemmGrid((CC + BN - 1)/BN, (NN + BM - 1)/BM);   // 17 x 79

    k_convertA<<<(NN*(size_t)NN/4 + 255)/256, 256>>>(A);

    // gconv 1: x = [inputs, states]
    k_buildX<<<(NN*CC + 255)/256, 256>>>(inputs, states, 0);
    k_gemmA<<<gemmGrid, 256>>>(0);                       // P1 = A @ X
    k_gemmA<<<gemmGrid, 256>>>(1);                       // P2 = 2 A @ P1 - X
    k_featRU<<<NN, 256>>>(W_ru, b_ru, states);           // sigmoid, r*s, u

    // gconv 2: x = [inputs, r*states]
    k_buildX<<<(NN*CC + 255)/256, 256>>>(inputs, states, 1);
    k_gemmA<<<gemmGrid, 256>>>(0);                       // Q1
    k_gemmA<<<gemmGrid, 256>>>(1);                       // Q2
    k_featC<<<NN, 256>>>(W_c, b_c, states, out);         // tanh + u*s + (1-u)*c
}